// round 12
// baseline (speedup 1.0000x reference)
#include <cuda_runtime.h>
#include <math.h>
#include <stdint.h>

#define BATCH  2
#define SLEN   2048
#define DMODEL 1024
#define HEADS  16
#define DHEAD  64
#define MTOT   (BATCH * SLEN)   // 4096

// ---------------- scratch (device globals; no allocation allowed) ----------
__device__ float g_q[MTOT * DMODEL];
__device__ float g_k[MTOT * DMODEL];
__device__ float g_v[MTOT * DMODEL];          // V TRANSPOSED: [b][h][d][s]
__device__ float g_ctx[MTOT * DMODEL];
__device__ float g_xc[MTOT * DMODEL];         // x pre-rounded to tf32
__device__ float g_wT[4 * DMODEL * DMODEL];   // wq^T, wk^T, wv^T, wo^T (tf32)

// ---------------- helpers ---------------------------------------------------
__device__ __forceinline__ uint32_t to_tf32(float x) {
    uint32_t r;
    asm("cvt.rna.tf32.f32 %0, %1;" : "=r"(r) : "f"(x));
    return r;
}
__device__ __forceinline__ void mma_tf32(float c[4], const uint32_t a[4],
                                         const uint32_t b[2]) {
    asm volatile(
        "mma.sync.aligned.m16n8k8.row.col.f32.tf32.tf32.f32 "
        "{%0,%1,%2,%3}, {%4,%5,%6,%7}, {%8,%9}, {%0,%1,%2,%3};"
        : "+f"(c[0]), "+f"(c[1]), "+f"(c[2]), "+f"(c[3])
        : "r"(a[0]), "r"(a[1]), "r"(a[2]), "r"(a[3]), "r"(b[0]), "r"(b[1]));
}
__device__ __forceinline__ void ldsm_x4(uint32_t r[4], const void* p) {
    uint32_t a = (uint32_t)__cvta_generic_to_shared(p);
    asm volatile(
        "ldmatrix.sync.aligned.m8n8.x4.shared.b16 {%0,%1,%2,%3}, [%4];"
        : "=r"(r[0]), "=r"(r[1]), "=r"(r[2]), "=r"(r[3]) : "r"(a));
}
__device__ __forceinline__ void cp_async16(void* dst, const void* src) {
    uint32_t d = (uint32_t)__cvta_generic_to_shared(dst);
    asm volatile("cp.async.cg.shared.global [%0], [%1], 16;" :: "r"(d), "l"(src));
}
__device__ __forceinline__ void cp_commit() { asm volatile("cp.async.commit_group;"); }
__device__ __forceinline__ void cp_wait1()  { asm volatile("cp.async.wait_group 1;"); }
__device__ __forceinline__ void cp_wait0()  { asm volatile("cp.async.wait_group 0;"); }

// ===========================================================================
// prep kernels
// ===========================================================================
__global__ __launch_bounds__(256) void cvt_x_kernel(const float* __restrict__ x)
{
    const size_t i = ((size_t)blockIdx.x * 256 + threadIdx.x) * 4;
    float4 v = *(const float4*)(x + i);
    v.x = __uint_as_float(to_tf32(v.x));
    v.y = __uint_as_float(to_tf32(v.y));
    v.z = __uint_as_float(to_tf32(v.z));
    v.w = __uint_as_float(to_tf32(v.w));
    *(float4*)(g_xc + i) = v;
}

__global__ __launch_bounds__(256) void transpose_cvt_kernel(
    const float* __restrict__ w0, const float* __restrict__ w1,
    const float* __restrict__ w2, const float* __restrict__ w3)
{
    __shared__ float tile[32][33];
    const int z = blockIdx.z;
    const float* src = (z == 0) ? w0 : (z == 1) ? w1 : (z == 2) ? w2 : w3;
    float* dst = g_wT + (size_t)z * DMODEL * DMODEL;

    const int tx = threadIdx.x, ty = threadIdx.y;
    const int k0 = blockIdx.y * 32, n0 = blockIdx.x * 32;

#pragma unroll
    for (int i = 0; i < 4; i++)
        tile[ty + 8 * i][tx] = src[(size_t)(k0 + ty + 8 * i) * DMODEL + n0 + tx];
    __syncthreads();
#pragma unroll
    for (int i = 0; i < 4; i++)
        dst[(size_t)(n0 + ty + 8 * i) * DMODEL + k0 + tx] =
            __uint_as_float(to_tf32(tile[tx][ty + 8 * i]));
}

// ===========================================================================
// tf32 GEMM, 3-stage cp.async ring, ONE barrier per k-tile.
// phase 0: QKV fused; z==2 (V) writes TRANSPOSED per-head [b][h][d][s].
// phase 1: output projection (+bias), fp32.
// ===========================================================================
#define GP 36
#define GT_SIZE (128 * GP)
#define GEMM_SMEM (6 * GT_SIZE * (int)sizeof(float))   // 110592 B

__global__ __launch_bounds__(256, 2) void gemm_kernel(
    const float* __restrict__ A, const float* __restrict__ wTbase,
    float* __restrict__ outQ, float* __restrict__ outK,
    float* __restrict__ outV, float* __restrict__ outO,
    const float* __restrict__ bias, int phase)
{
    extern __shared__ float sm[];
    float* Ab[3] = { sm,           sm + 2*GT_SIZE, sm + 4*GT_SIZE };
    float* Bb[3] = { sm + GT_SIZE, sm + 3*GT_SIZE, sm + 5*GT_SIZE };

    const int z = blockIdx.z;
    const size_t WSZ = (size_t)DMODEL * DMODEL;
    const float* BT;
    float scale = 1.f;
    int roundOut;
    float* C;
    if (phase == 0) {
        BT = wTbase + (size_t)z * WSZ;
        roundOut = 1;
        // Q scale folds 1/sqrt(64) AND log2(e) for the exp2-based softmax
        if (z == 0)      { C = outQ; scale = 0.125f * 1.4426950408889634f; }
        else if (z == 1) { C = outK; }
        else             { C = outV; }
    } else {
        BT = wTbase + 3 * WSZ;
        C = outO; roundOut = 0;
    }

    const int t    = threadIdx.x;
    const int lane = t & 31;
    const int warp = t >> 5;
    const int m0   = blockIdx.y * 128;
    const int n0   = blockIdx.x * 128;
    const int wm   = (warp & 3) * 32;
    const int wn   = (warp >> 2) * 64;
    const int N = DMODEL, K = DMODEL;

    const int sr = t >> 3;
    const int sc = (t & 7) << 2;

    const float* Ag = A  + (size_t)m0 * K + sc;
    const float* Bg = BT + (size_t)n0 * K + sc;

    float acc[2][8][4];
#pragma unroll
    for (int mi = 0; mi < 2; mi++)
#pragma unroll
        for (int ni = 0; ni < 8; ni++)
#pragma unroll
            for (int r = 0; r < 4; r++) acc[mi][ni][r] = 0.f;

    const int nt = K / 32;

    auto stage = [&](int kt, int buf) {
        const int koff = kt * 32;
#pragma unroll
        for (int i = 0; i < 4; i++) {
            const int r = sr + i * 32;
            cp_async16(&Ab[buf][r * GP + sc], Ag + (size_t)r * K + koff);
            cp_async16(&Bb[buf][r * GP + sc], Bg + (size_t)r * K + koff);
        }
    };

    stage(0, 0); cp_commit();
    stage(1, 1); cp_commit();

    for (int kt = 0; kt < nt; kt++) {
        if (kt < nt - 1) cp_wait1(); else cp_wait0();
        __syncthreads();

        const int cur = kt - (kt / 3) * 3;   // kt % 3
        const float* As = Ab[cur];
        const float* Bs = Bb[cur];
        const float* abase = As + (lane & 15) * GP + ((lane >> 4) << 2);
        const float* bbase = Bs + (((lane >> 4) << 3) + (lane & 7)) * GP
                             + (((lane >> 3) & 1) << 2);
#pragma unroll
        for (int ks = 0; ks < 4; ks++) {
            const int k0 = ks * 8;
            uint32_t afr[2][4];
#pragma unroll
            for (int mi = 0; mi < 2; mi++)
                ldsm_x4(afr[mi], abase + (wm + mi * 16) * GP + k0);
#pragma unroll
            for (int np = 0; np < 4; np++) {
                uint32_t bfr[4];
                ldsm_x4(bfr, bbase + (wn + np * 16) * GP + k0);
#pragma unroll
                for (int mi = 0; mi < 2; mi++) {
                    mma_tf32(acc[mi][2 * np],     afr[mi], bfr);
                    mma_tf32(acc[mi][2 * np + 1], afr[mi], bfr + 2);
                }
            }
        }

        if (kt + 2 < nt) {
            const int nb = (kt + 2) - ((kt + 2) / 3) * 3;
            stage(kt + 2, nb);
            cp_commit();
        }
    }

    const bool vtrans = (phase == 0 && z == 2);
#pragma unroll
    for (int mi = 0; mi < 2; mi++) {
        const int row0 = m0 + wm + mi * 16 + (lane >> 2);
#pragma unroll
        for (int ni = 0; ni < 8; ni++) {
            const int col = n0 + wn + ni * 8 + ((lane & 3) << 1);
            float b0 = 0.f, b1 = 0.f;
            if (phase == 1 && bias) { b0 = bias[col]; b1 = bias[col + 1]; }
            float v00 = acc[mi][ni][0] * scale + b0;
            float v01 = acc[mi][ni][1] * scale + b1;
            float v10 = acc[mi][ni][2] * scale + b0;
            float v11 = acc[mi][ni][3] * scale + b1;
            if (roundOut) {
                v00 = __uint_as_float(to_tf32(v00));
                v01 = __uint_as_float(to_tf32(v01));
                v10 = __uint_as_float(to_tf32(v10));
                v11 = __uint_as_float(to_tf32(v11));
            }
            if (vtrans) {
                const int bb = row0 >> 11;          // / SLEN
                const int s  = row0 & (SLEN - 1);
                const int h  = col >> 6;
                const int d  = col & 63;
                float* vt = C + (((size_t)bb * HEADS + h) * DHEAD + d) * SLEN + s;
                vt[0]        = v00;
                vt[SLEN]     = v01;
                vt[8]        = v10;
                vt[SLEN + 8] = v11;
            } else {
                float2 a = {v00, v01}, b = {v10, v11};
                *(float2*)(C + (size_t)row0 * N + col) = a;
                *(float2*)(C + (size_t)(row0 + 8) * N + col) = b;
            }
        }
    }
}

// ===========================================================================
// Causal flash attention, tf32 mma. BQ=128, BK=64, 256 thr (8 warps).
// Batched fragment loads (4-5 ldsm then 8 mma) to hide LDS latency under
// the volatile-asm ordering. exp2-based softmax (log2e folded into Q).
// Fully-masked n-tiles skipped per warp (nact). V pre-transposed per head.
// ===========================================================================
#define AP 68
#define ATTN_SMEM ((128 + 4 * 64) * AP * (int)sizeof(float))   // 104448 B

__global__ __launch_bounds__(256, 2) void attn_kernel()
{
    extern __shared__ float smf[];
    float* QPs = smf;                          // 128 x AP
    float* KsB[2]  = { smf + 128 * AP, smf + 256 * AP };
    float* VTsB[2] = { smf + 192 * AP, smf + 320 * AP };

    const int qt   = gridDim.x - 1 - blockIdx.x;   // heavy tiles first
    const int h    = blockIdx.y;
    const int b    = blockIdx.z;
    const int t    = threadIdx.x;
    const int lane = t & 31;
    const int w    = t >> 5;
    const int wbase = w * 16;

    const float* Qg  = g_q + ((size_t)b * SLEN + qt * 128) * DMODEL + h * DHEAD;
    const float* Kg  = g_k + (size_t)b * SLEN * DMODEL + h * DHEAD;
    const float* VTg = g_v + ((size_t)b * HEADS + h) * DHEAD * SLEN;  // [d][s]

    const int strow = t >> 4;            // 0..15
    const int stcol = (t & 15) << 2;     // 0..60
    const int vrow  = t >> 2;            // 0..63 (d)
    const int vcol4 = t & 3;

    auto stageKV = [&](int kt, int buf) {
#pragma unroll
        for (int i = 0; i < 4; i++) {
            const int r = strow + 16 * i;
            cp_async16(KsB[buf] + r * AP + stcol,
                       Kg + (size_t)(kt * 64 + r) * DMODEL + stcol);
        }
#pragma unroll
        for (int i = 0; i < 4; i++) {
            const int c = (vcol4 + 4 * i) << 2;
            cp_async16(VTsB[buf] + vrow * AP + c,
                       VTg + (size_t)vrow * SLEN + kt * 64 + c);
        }
    };

    // ---- stage Q (plain loads; already tf32) ----
#pragma unroll
    for (int i = 0; i < 8; i++) {
        const int r = strow + 16 * i;
        *(float4*)(QPs + r * AP + stcol) =
            *(const float4*)(Qg + (size_t)r * DMODEL + stcol);
    }

    stageKV(0, 0);
    cp_commit();
    __syncthreads();

    // ---- Q fragments into registers (QPs then free for P) ----
    uint32_t qa[8][4];
    {
        const float* base = QPs + (wbase + (lane & 15)) * AP + ((lane >> 4) << 2);
#pragma unroll
        for (int ds = 0; ds < 8; ds++)
            ldsm_x4(qa[ds], base + ds * 8);
    }

    float m0 = -1e30f, m1 = -1e30f, l0 = 0.f, l1 = 0.f;
    float O[8][4];
#pragma unroll
    for (int dn = 0; dn < 8; dn++)
#pragma unroll
        for (int r = 0; r < 4; r++) O[dn][r] = 0.f;

    const int r0 = lane >> 2;
    const int q2 = (lane & 3) << 1;
    const int ktmax = 2 * qt + 1;

    for (int kt = 0; kt <= ktmax; kt++) {
        if (kt < ktmax) { stageKV(kt + 1, (kt + 1) & 1); cp_commit(); cp_wait1(); }
        else            { cp_wait0(); }
        __syncthreads();

        const float* Ks  = KsB[kt & 1];
        const float* VTs = VTsB[kt & 1];
        const int off = kt * 64 - qt * 128;

        if (off <= wbase + 15) {
            // active n-tiles for this warp (warp-uniform)
            const int span = wbase + 15 - off;                  // >= 0 here
            const int nact = (span >> 3) >= 7 ? 8 : (span >> 3) + 1;
            const int npact = (nact + 1) >> 1;

            // ---- S = Q @ K^T  (batched: 4 ldsm then 8 mma per ds) ----
            float sacc[8][4];
#pragma unroll
            for (int n = 0; n < 8; n++)
#pragma unroll
                for (int r = 0; r < 4; r++) sacc[n][r] = 0.f;
            {
                const float* kbase = Ks + (((lane >> 4) << 3) + (lane & 7)) * AP
                                     + (((lane >> 3) & 1) << 2);
#pragma unroll
                for (int ds = 0; ds < 8; ds++) {
                    uint32_t kb[4][4];
                    for (int np = 0; np < npact; np++)
                        ldsm_x4(kb[np], kbase + np * 16 * AP + ds * 8);
                    for (int np = 0; np < npact; np++) {
                        mma_tf32(sacc[2 * np],     qa[ds], kb[np]);
                        mma_tf32(sacc[2 * np + 1], qa[ds], kb[np] + 2);
                    }
                }
            }

            // ---- causal mask (boundary tiles) ----
            if (off + 63 > wbase) {
                const int rg0 = wbase + r0;
                const int rg1 = rg0 + 8;
                for (int n = 0; n < nact; n++) {
                    int c0 = off + n * 8 + q2;
                    if (c0     > rg0) sacc[n][0] = -1e30f;
                    if (c0 + 1 > rg0) sacc[n][1] = -1e30f;
                    if (c0     > rg1) sacc[n][2] = -1e30f;
                    if (c0 + 1 > rg1) sacc[n][3] = -1e30f;
                }
            }

            // ---- online softmax (base-2 domain) ----
            float mx0 = -1e30f, mx1 = -1e30f;
            for (int n = 0; n < nact; n++) {
                mx0 = fmaxf(mx0, fmaxf(sacc[n][0], sacc[n][1]));
                mx1 = fmaxf(mx1, fmaxf(sacc[n][2], sacc[n][3]));
            }
            mx0 = fmaxf(mx0, __shfl_xor_sync(0xffffffffu, mx0, 1));
            mx0 = fmaxf(mx0, __shfl_xor_sync(0xffffffffu, mx0, 2));
            mx1 = fmaxf(mx1, __shfl_xor_sync(0xffffffffu, mx1, 1));
            mx1 = fmaxf(mx1, __shfl_xor_sync(0xffffffffu, mx1, 2));

            const float nm0 = fmaxf(m0, mx0);
            const float nm1 = fmaxf(m1, mx1);
            const float a0  = exp2f(m0 - nm0);
            const float a1  = exp2f(m1 - nm1);
            float s0 = 0.f, s1 = 0.f;

            float* Prow0 = QPs + (wbase + r0) * AP + q2;
            float* Prow1 = Prow0 + 8 * AP;
            for (int n = 0; n < nact; n++) {
                float p00 = exp2f(sacc[n][0] - nm0);
                float p01 = exp2f(sacc[n][1] - nm0);
                float p10 = exp2f(sacc[n][2] - nm1);
                float p11 = exp2f(sacc[n][3] - nm1);
                s0 += p00 + p01;
                s1 += p10 + p11;
                float2 lo, hi;
                lo.x = __uint_as_float(to_tf32(p00));
                lo.y = __uint_as_float(to_tf32(p01));
                hi.x = __uint_as_float(to_tf32(p10));
                hi.y = __uint_as_float(to_tf32(p11));
                *(float2*)(Prow0 + n * 8) = lo;
                *(float2*)(Prow1 + n * 8) = hi;
            }
            s0 += __shfl_xor_sync(0xffffffffu, s0, 1);
            s0 += __shfl_xor_sync(0xffffffffu, s0, 2);
            s1 += __shfl_xor_sync(0xffffffffu, s1, 1);
            s1 += __shfl_xor_sync(0xffffffffu, s1, 2);

            l0 = l0 * a0 + s0;
            l1 = l1 * a1 + s1;
            m0 = nm0;
            m1 = nm1;
#pragma unroll
            for (int dn = 0; dn < 8; dn++) {
                O[dn][0] *= a0; O[dn][1] *= a0;
                O[dn][2] *= a1; O[dn][3] *= a1;
            }
            __syncwarp();

            // ---- O += P @ V  (batched: 5 ldsm then 8 mma per ks) ----
            {
                const float* pbase = QPs + (wbase + (lane & 15)) * AP
                                     + ((lane >> 4) << 2);
                const float* vtbase = VTs + (((lane >> 4) << 3) + (lane & 7)) * AP
                                      + (((lane >> 3) & 1) << 2);
                for (int ks = 0; ks < nact; ks++) {
                    uint32_t pa[4];
                    uint32_t vb[4][4];
                    ldsm_x4(pa, pbase + ks * 8);
#pragma unroll
                    for (int np = 0; np < 4; np++)
                        ldsm_x4(vb[np], vtbase + np * 16 * AP + ks * 8);
#pragma unroll
                    for (int np = 0; np < 4; np++) {
                        mma_tf32(O[2 * np],     pa, vb[np]);
                        mma_tf32(O[2 * np + 1], pa, vb[np] + 2);
                    }
                }
            }
        }
        __syncthreads();   // buffer reads done before overwrite next iter
    }

    // ---- finalize & write context (tf32-rounded for the wo GEMM) ----
    const float inv0 = 1.f / l0;
    const float inv1 = 1.f / l1;
    const int rg0 = qt * 128 + wbase + r0;
    float* C0 = g_ctx + ((size_t)b * SLEN + rg0) * DMODEL + h * DHEAD + q2;
    float* C1 = C0 + 8 * DMODEL;
#pragma unroll
    for (int dn = 0; dn < 8; dn++) {
        float2 v0, v1;
        v0.x = __uint_as_float(to_tf32(O[dn][0] * inv0));
        v0.y = __uint_as_float(to_tf32(O[dn][1] * inv0));
        v1.x = __uint_as_float(to_tf32(O[dn][2] * inv1));
        v1.y = __uint_as_float(to_tf32(O[dn][3] * inv1));
        *(float2*)(C0 + dn * 8) = v0;
        *(float2*)(C1 + dn * 8) = v1;
    }
}

// ---------------------------------------------------------------------------
extern "C" void kernel_launch(void* const* d_in, const int* in_sizes, int n_in,
                              void* d_out, int out_size)
{
    const float* x  = (const float*)d_in[0];
    const float* wq = (const float*)d_in[1];
    const float* wk = (const float*)d_in[2];
    const float* wv = (const float*)d_in[3];
    const float* wo = (const float*)d_in[4];
    const float* bo = (const float*)d_in[5];
    float* out = (float*)d_out;

    void *pq, *pk, *pv, *pctx, *pwT, *pxc;
    cudaGetSymbolAddress(&pq,   g_q);
    cudaGetSymbolAddress(&pk,   g_k);
    cudaGetSymbolAddress(&pv,   g_v);
    cudaGetSymbolAddress(&pctx, g_ctx);
    cudaGetSymbolAddress(&pwT,  g_wT);
    cudaGetSymbolAddress(&pxc,  g_xc);

    cudaFuncSetAttribute(attn_kernel,
                         cudaFuncAttributeMaxDynamicSharedMemorySize, ATTN_SMEM);
    cudaFuncSetAttribute(gemm_kernel,
                         cudaFuncAttributeMaxDynamicSharedMemorySize, GEMM_SMEM);

    transpose_cvt_kernel<<<dim3(32, 32, 4), dim3(32, 8)>>>(wq, wk, wv, wo);
    cvt_x_kernel<<<(MTOT * DMODEL) / (256 * 4), 256>>>(x);

    dim3 gblk(256);

    // fused QKV projections (z selects weight/output; V written transposed;
    // Q scale carries 0.125 * log2(e) for the exp2 softmax)
    gemm_kernel<<<dim3(DMODEL / 128, MTOT / 128, 3), gblk, GEMM_SMEM>>>(
        (const float*)pxc, (const float*)pwT,
        (float*)pq, (float*)pk, (float*)pv, nullptr, nullptr, 0);

    // causal flash attention
    attn_kernel<<<dim3(SLEN / 128, HEADS, BATCH), 256, ATTN_SMEM>>>();

    // output projection + bias
    gemm_kernel<<<dim3(DMODEL / 128, MTOT / 128, 1), gblk, GEMM_SMEM>>>(
        (const float*)pctx, (const float*)pwT,
        nullptr, nullptr, nullptr, out, bo, 1);
}

// round 15
// speedup vs baseline: 2.8689x; 2.8689x over previous
#include <cuda_runtime.h>
#include <math.h>
#include <stdint.h>

#define BATCH  2
#define SLEN   2048
#define DMODEL 1024
#define HEADS  16
#define DHEAD  64
#define MTOT   (BATCH * SLEN)   // 4096

// ---------------- scratch (device globals; no allocation allowed) ----------
__device__ float g_q[MTOT * DMODEL];
__device__ float g_k[MTOT * DMODEL];
__device__ float g_v[MTOT * DMODEL];          // V TRANSPOSED: [b][h][d][s]
__device__ float g_ctx[MTOT * DMODEL];
__device__ float g_xc[MTOT * DMODEL];         // x pre-rounded to tf32
__device__ float g_wT[4 * DMODEL * DMODEL];   // wq^T, wk^T, wv^T, wo^T (tf32)

// ---------------- helpers ---------------------------------------------------
__device__ __forceinline__ uint32_t to_tf32(float x) {
    uint32_t r;
    asm("cvt.rna.tf32.f32 %0, %1;" : "=r"(r) : "f"(x));
    return r;
}
__device__ __forceinline__ void mma_tf32(float c[4], const uint32_t a[4],
                                         const uint32_t b[2]) {
    asm volatile(
        "mma.sync.aligned.m16n8k8.row.col.f32.tf32.tf32.f32 "
        "{%0,%1,%2,%3}, {%4,%5,%6,%7}, {%8,%9}, {%0,%1,%2,%3};"
        : "+f"(c[0]), "+f"(c[1]), "+f"(c[2]), "+f"(c[3])
        : "r"(a[0]), "r"(a[1]), "r"(a[2]), "r"(a[3]), "r"(b[0]), "r"(b[1]));
}
__device__ __forceinline__ void ldsm_x4(uint32_t r[4], const void* p) {
    uint32_t a = (uint32_t)__cvta_generic_to_shared(p);
    asm volatile(
        "ldmatrix.sync.aligned.m8n8.x4.shared.b16 {%0,%1,%2,%3}, [%4];"
        : "=r"(r[0]), "=r"(r[1]), "=r"(r[2]), "=r"(r[3]) : "r"(a));
}
__device__ __forceinline__ void cp_async16(void* dst, const void* src) {
    uint32_t d = (uint32_t)__cvta_generic_to_shared(dst);
    asm volatile("cp.async.cg.shared.global [%0], [%1], 16;" :: "r"(d), "l"(src));
}
__device__ __forceinline__ void cp_commit() { asm volatile("cp.async.commit_group;"); }
__device__ __forceinline__ void cp_wait1()  { asm volatile("cp.async.wait_group 1;"); }
__device__ __forceinline__ void cp_wait0()  { asm volatile("cp.async.wait_group 0;"); }

// ===========================================================================
// prep kernels
// ===========================================================================
__global__ __launch_bounds__(256) void cvt_x_kernel(const float* __restrict__ x)
{
    const size_t i = ((size_t)blockIdx.x * 256 + threadIdx.x) * 4;
    float4 v = *(const float4*)(x + i);
    v.x = __uint_as_float(to_tf32(v.x));
    v.y = __uint_as_float(to_tf32(v.y));
    v.z = __uint_as_float(to_tf32(v.z));
    v.w = __uint_as_float(to_tf32(v.w));
    *(float4*)(g_xc + i) = v;
}

__global__ __launch_bounds__(256) void transpose_cvt_kernel(
    const float* __restrict__ w0, const float* __restrict__ w1,
    const float* __restrict__ w2, const float* __restrict__ w3)
{
    __shared__ float tile[32][33];
    const int z = blockIdx.z;
    const float* src = (z == 0) ? w0 : (z == 1) ? w1 : (z == 2) ? w2 : w3;
    float* dst = g_wT + (size_t)z * DMODEL * DMODEL;

    const int tx = threadIdx.x, ty = threadIdx.y;
    const int k0 = blockIdx.y * 32, n0 = blockIdx.x * 32;

#pragma unroll
    for (int i = 0; i < 4; i++)
        tile[ty + 8 * i][tx] = src[(size_t)(k0 + ty + 8 * i) * DMODEL + n0 + tx];
    __syncthreads();
#pragma unroll
    for (int i = 0; i < 4; i++)
        dst[(size_t)(n0 + ty + 8 * i) * DMODEL + k0 + tx] =
            __uint_as_float(to_tf32(tile[tx][ty + 8 * i]));
}

// ===========================================================================
// tf32 GEMM, 3-stage cp.async ring, ONE barrier per k-tile.
// phase 0: QKV fused; z==2 (V) writes TRANSPOSED per-head [b][h][d][s].
// phase 1: output projection (+bias), fp32.
// ===========================================================================
#define GP 36
#define GT_SIZE (128 * GP)
#define GEMM_SMEM (6 * GT_SIZE * (int)sizeof(float))   // 110592 B

__global__ __launch_bounds__(256, 2) void gemm_kernel(
    const float* __restrict__ A, const float* __restrict__ wTbase,
    float* __restrict__ outQ, float* __restrict__ outK,
    float* __restrict__ outV, float* __restrict__ outO,
    const float* __restrict__ bias, int phase)
{
    extern __shared__ float sm[];
    float* Ab[3] = { sm,           sm + 2*GT_SIZE, sm + 4*GT_SIZE };
    float* Bb[3] = { sm + GT_SIZE, sm + 3*GT_SIZE, sm + 5*GT_SIZE };

    const int z = blockIdx.z;
    const size_t WSZ = (size_t)DMODEL * DMODEL;
    const float* BT;
    float scale = 1.f;
    int roundOut;
    float* C;
    if (phase == 0) {
        BT = wTbase + (size_t)z * WSZ;
        roundOut = 1;
        // Q scale folds 1/sqrt(64) AND log2(e) for the exp2-based softmax
        if (z == 0)      { C = outQ; scale = 0.125f * 1.4426950408889634f; }
        else if (z == 1) { C = outK; }
        else             { C = outV; }
    } else {
        BT = wTbase + 3 * WSZ;
        C = outO; roundOut = 0;
    }

    const int t    = threadIdx.x;
    const int lane = t & 31;
    const int warp = t >> 5;
    const int m0   = blockIdx.y * 128;
    const int n0   = blockIdx.x * 128;
    const int wm   = (warp & 3) * 32;
    const int wn   = (warp >> 2) * 64;
    const int N = DMODEL, K = DMODEL;

    const int sr = t >> 3;
    const int sc = (t & 7) << 2;

    const float* Ag = A  + (size_t)m0 * K + sc;
    const float* Bg = BT + (size_t)n0 * K + sc;

    float acc[2][8][4];
#pragma unroll
    for (int mi = 0; mi < 2; mi++)
#pragma unroll
        for (int ni = 0; ni < 8; ni++)
#pragma unroll
            for (int r = 0; r < 4; r++) acc[mi][ni][r] = 0.f;

    const int nt = K / 32;

    auto stage = [&](int kt, int buf) {
        const int koff = kt * 32;
#pragma unroll
        for (int i = 0; i < 4; i++) {
            const int r = sr + i * 32;
            cp_async16(&Ab[buf][r * GP + sc], Ag + (size_t)r * K + koff);
            cp_async16(&Bb[buf][r * GP + sc], Bg + (size_t)r * K + koff);
        }
    };

    stage(0, 0); cp_commit();
    stage(1, 1); cp_commit();

    for (int kt = 0; kt < nt; kt++) {
        if (kt < nt - 1) cp_wait1(); else cp_wait0();
        __syncthreads();

        const int cur = kt - (kt / 3) * 3;   // kt % 3
        const float* As = Ab[cur];
        const float* Bs = Bb[cur];
        const float* abase = As + (lane & 15) * GP + ((lane >> 4) << 2);
        const float* bbase = Bs + (((lane >> 4) << 3) + (lane & 7)) * GP
                             + (((lane >> 3) & 1) << 2);
#pragma unroll
        for (int ks = 0; ks < 4; ks++) {
            const int k0 = ks * 8;
            uint32_t afr[2][4];
#pragma unroll
            for (int mi = 0; mi < 2; mi++)
                ldsm_x4(afr[mi], abase + (wm + mi * 16) * GP + k0);
#pragma unroll
            for (int np = 0; np < 4; np++) {
                uint32_t bfr[4];
                ldsm_x4(bfr, bbase + (wn + np * 16) * GP + k0);
#pragma unroll
                for (int mi = 0; mi < 2; mi++) {
                    mma_tf32(acc[mi][2 * np],     afr[mi], bfr);
                    mma_tf32(acc[mi][2 * np + 1], afr[mi], bfr + 2);
                }
            }
        }

        if (kt + 2 < nt) {
            const int nb = (kt + 2) - ((kt + 2) / 3) * 3;
            stage(kt + 2, nb);
            cp_commit();
        }
    }

    const bool vtrans = (phase == 0 && z == 2);
#pragma unroll
    for (int mi = 0; mi < 2; mi++) {
        const int row0 = m0 + wm + mi * 16 + (lane >> 2);
#pragma unroll
        for (int ni = 0; ni < 8; ni++) {
            const int col = n0 + wn + ni * 8 + ((lane & 3) << 1);
            float b0 = 0.f, b1 = 0.f;
            if (phase == 1 && bias) { b0 = bias[col]; b1 = bias[col + 1]; }
            float v00 = acc[mi][ni][0] * scale + b0;
            float v01 = acc[mi][ni][1] * scale + b1;
            float v10 = acc[mi][ni][2] * scale + b0;
            float v11 = acc[mi][ni][3] * scale + b1;
            if (roundOut) {
                v00 = __uint_as_float(to_tf32(v00));
                v01 = __uint_as_float(to_tf32(v01));
                v10 = __uint_as_float(to_tf32(v10));
                v11 = __uint_as_float(to_tf32(v11));
            }
            if (vtrans) {
                const int bb = row0 >> 11;          // / SLEN
                const int s  = row0 & (SLEN - 1);
                const int h  = col >> 6;
                const int d  = col & 63;
                float* vt = C + (((size_t)bb * HEADS + h) * DHEAD + d) * SLEN + s;
                vt[0]        = v00;
                vt[SLEN]     = v01;
                vt[8]        = v10;
                vt[SLEN + 8] = v11;
            } else {
                float2 a = {v00, v01}, b = {v10, v11};
                *(float2*)(C + (size_t)row0 * N + col) = a;
                *(float2*)(C + (size_t)(row0 + 8) * N + col) = b;
            }
        }
    }
}

// ===========================================================================
// Causal flash attention, tf32 mma. BQ=128, BK=64, 256 thr (8 warps).
// Batched ldsm, fully static unrolled loops (no predication). exp2 softmax.
// V pre-transposed per head ([d][s]) -> PV symmetric with QK via ldmatrix.
// ===========================================================================
#define AP 68
#define ATTN_SMEM ((128 + 4 * 64) * AP * (int)sizeof(float))   // 104448 B

__global__ __launch_bounds__(256, 2) void attn_kernel()
{
    extern __shared__ float smf[];
    float* QPs = smf;                          // 128 x AP
    float* KsB[2]  = { smf + 128 * AP, smf + 256 * AP };
    float* VTsB[2] = { smf + 192 * AP, smf + 320 * AP };

    const int qt   = gridDim.x - 1 - blockIdx.x;   // heavy tiles first
    const int h    = blockIdx.y;
    const int b    = blockIdx.z;
    const int t    = threadIdx.x;
    const int lane = t & 31;
    const int w    = t >> 5;
    const int wbase = w * 16;

    const float* Qg  = g_q + ((size_t)b * SLEN + qt * 128) * DMODEL + h * DHEAD;
    const float* Kg  = g_k + (size_t)b * SLEN * DMODEL + h * DHEAD;
    const float* VTg = g_v + ((size_t)b * HEADS + h) * DHEAD * SLEN;  // [d][s]

    const int strow = t >> 4;            // 0..15
    const int stcol = (t & 15) << 2;     // 0..60
    const int vrow  = t >> 2;            // 0..63 (d)
    const int vcol4 = t & 3;

    auto stageKV = [&](int kt, int buf) {
#pragma unroll
        for (int i = 0; i < 4; i++) {
            const int r = strow + 16 * i;
            cp_async16(KsB[buf] + r * AP + stcol,
                       Kg + (size_t)(kt * 64 + r) * DMODEL + stcol);
        }
#pragma unroll
        for (int i = 0; i < 4; i++) {
            const int c = (vcol4 + 4 * i) << 2;
            cp_async16(VTsB[buf] + vrow * AP + c,
                       VTg + (size_t)vrow * SLEN + kt * 64 + c);
        }
    };

    // ---- stage Q (plain loads; already tf32) ----
#pragma unroll
    for (int i = 0; i < 8; i++) {
        const int r = strow + 16 * i;
        *(float4*)(QPs + r * AP + stcol) =
            *(const float4*)(Qg + (size_t)r * DMODEL + stcol);
    }

    stageKV(0, 0);
    cp_commit();
    __syncthreads();

    // ---- Q fragments into registers (QPs then free for P) ----
    uint32_t qa[8][4];
    {
        const float* base = QPs + (wbase + (lane & 15)) * AP + ((lane >> 4) << 2);
#pragma unroll
        for (int ds = 0; ds < 8; ds++)
            ldsm_x4(qa[ds], base + ds * 8);
    }

    float m0 = -1e30f, m1 = -1e30f, l0 = 0.f, l1 = 0.f;
    float O[8][4];
#pragma unroll
    for (int dn = 0; dn < 8; dn++)
#pragma unroll
        for (int r = 0; r < 4; r++) O[dn][r] = 0.f;

    const int r0 = lane >> 2;
    const int q2 = (lane & 3) << 1;
    const int ktmax = 2 * qt + 1;

    for (int kt = 0; kt <= ktmax; kt++) {
        if (kt < ktmax) { stageKV(kt + 1, (kt + 1) & 1); cp_commit(); cp_wait1(); }
        else            { cp_wait0(); }
        __syncthreads();

        const float* Ks  = KsB[kt & 1];
        const float* VTs = VTsB[kt & 1];
        const int off = kt * 64 - qt * 128;

        if (off <= wbase + 15) {
            // ---- S = Q @ K^T  (ds-outer: 4 ldsm then 8 mma) ----
            float sacc[8][4];
#pragma unroll
            for (int n = 0; n < 8; n++)
#pragma unroll
                for (int r = 0; r < 4; r++) sacc[n][r] = 0.f;
            {
                const float* kbase = Ks + (((lane >> 4) << 3) + (lane & 7)) * AP
                                     + (((lane >> 3) & 1) << 2);
#pragma unroll
                for (int ds = 0; ds < 8; ds++) {
                    uint32_t kb[4][4];
#pragma unroll
                    for (int np = 0; np < 4; np++)
                        ldsm_x4(kb[np], kbase + np * 16 * AP + ds * 8);
#pragma unroll
                    for (int np = 0; np < 4; np++) {
                        mma_tf32(sacc[2 * np],     qa[ds], kb[np]);
                        mma_tf32(sacc[2 * np + 1], qa[ds], kb[np] + 2);
                    }
                }
            }

            // ---- causal mask (boundary tiles) ----
            if (off + 63 > wbase) {
                const int rg0 = wbase + r0;
                const int rg1 = rg0 + 8;
#pragma unroll
                for (int n = 0; n < 8; n++) {
                    int c0 = off + n * 8 + q2;
                    if (c0     > rg0) sacc[n][0] = -1e30f;
                    if (c0 + 1 > rg0) sacc[n][1] = -1e30f;
                    if (c0     > rg1) sacc[n][2] = -1e30f;
                    if (c0 + 1 > rg1) sacc[n][3] = -1e30f;
                }
            }

            // ---- online softmax (base-2 domain) ----
            float mx0 = -1e30f, mx1 = -1e30f;
#pragma unroll
            for (int n = 0; n < 8; n++) {
                mx0 = fmaxf(mx0, fmaxf(sacc[n][0], sacc[n][1]));
                mx1 = fmaxf(mx1, fmaxf(sacc[n][2], sacc[n][3]));
            }
            mx0 = fmaxf(mx0, __shfl_xor_sync(0xffffffffu, mx0, 1));
            mx0 = fmaxf(mx0, __shfl_xor_sync(0xffffffffu, mx0, 2));
            mx1 = fmaxf(mx1, __shfl_xor_sync(0xffffffffu, mx1, 1));
            mx1 = fmaxf(mx1, __shfl_xor_sync(0xffffffffu, mx1, 2));

            const float nm0 = fmaxf(m0, mx0);
            const float nm1 = fmaxf(m1, mx1);
            const float a0  = exp2f(m0 - nm0);
            const float a1  = exp2f(m1 - nm1);
            float s0 = 0.f, s1 = 0.f;

            float* Prow0 = QPs + (wbase + r0) * AP + q2;
            float* Prow1 = Prow0 + 8 * AP;
#pragma unroll
            for (int n = 0; n < 8; n++) {
                float p00 = exp2f(sacc[n][0] - nm0);
                float p01 = exp2f(sacc[n][1] - nm0);
                float p10 = exp2f(sacc[n][2] - nm1);
                float p11 = exp2f(sacc[n][3] - nm1);
                s0 += p00 + p01;
                s1 += p10 + p11;
                float2 lo, hi;
                lo.x = __uint_as_float(to_tf32(p00));
                lo.y = __uint_as_float(to_tf32(p01));
                hi.x = __uint_as_float(to_tf32(p10));
                hi.y = __uint_as_float(to_tf32(p11));
                *(float2*)(Prow0 + n * 8) = lo;
                *(float2*)(Prow1 + n * 8) = hi;
            }
            s0 += __shfl_xor_sync(0xffffffffu, s0, 1);
            s0 += __shfl_xor_sync(0xffffffffu, s0, 2);
            s1 += __shfl_xor_sync(0xffffffffu, s1, 1);
            s1 += __shfl_xor_sync(0xffffffffu, s1, 2);

            l0 = l0 * a0 + s0;
            l1 = l1 * a1 + s1;
            m0 = nm0;
            m1 = nm1;
#pragma unroll
            for (int dn = 0; dn < 8; dn++) {
                O[dn][0] *= a0; O[dn][1] *= a0;
                O[dn][2] *= a1; O[dn][3] *= a1;
            }
            __syncwarp();

            // ---- O += P @ V  (ks-outer: 5 ldsm then 8 mma) ----
            {
                const float* pbase = QPs + (wbase + (lane & 15)) * AP
                                     + ((lane >> 4) << 2);
                const float* vtbase = VTs + (((lane >> 4) << 3) + (lane & 7)) * AP
                                      + (((lane >> 3) & 1) << 2);
#pragma unroll
                for (int ks = 0; ks < 8; ks++) {
                    uint32_t pa[4];
                    uint32_t vb[4][4];
                    ldsm_x4(pa, pbase + ks * 8);
#pragma unroll
                    for (int np = 0; np < 4; np++)
                        ldsm_x4(vb[np], vtbase + np * 16 * AP + ks * 8);
#pragma unroll
                    for (int np = 0; np < 4; np++) {
                        mma_tf32(O[2 * np],     pa, vb[np]);
                        mma_tf32(O[2 * np + 1], pa, vb[np] + 2);
                    }
                }
            }
        }
        __syncthreads();   // buffer reads done before overwrite next iter
    }

    // ---- finalize & write context (tf32-rounded for the wo GEMM) ----
    const float inv0 = 1.f / l0;
    const float inv1 = 1.f / l1;
    const int rg0 = qt * 128 + wbase + r0;
    float* C0 = g_ctx + ((size_t)b * SLEN + rg0) * DMODEL + h * DHEAD + q2;
    float* C1 = C0 + 8 * DMODEL;
#pragma unroll
    for (int dn = 0; dn < 8; dn++) {
        float2 v0, v1;
        v0.x = __uint_as_float(to_tf32(O[dn][0] * inv0));
        v0.y = __uint_as_float(to_tf32(O[dn][1] * inv0));
        v1.x = __uint_as_float(to_tf32(O[dn][2] * inv1));
        v1.y = __uint_as_float(to_tf32(O[dn][3] * inv1));
        *(float2*)(C0 + dn * 8) = v0;
        *(float2*)(C1 + dn * 8) = v1;
    }
}

// ---------------------------------------------------------------------------
extern "C" void kernel_launch(void* const* d_in, const int* in_sizes, int n_in,
                              void* d_out, int out_size)
{
    const float* x  = (const float*)d_in[0];
    const float* wq = (const float*)d_in[1];
    const float* wk = (const float*)d_in[2];
    const float* wv = (const float*)d_in[3];
    const float* wo = (const float*)d_in[4];
    const float* bo = (const float*)d_in[5];
    float* out = (float*)d_out;

    void *pq, *pk, *pv, *pctx, *pwT, *pxc;
    cudaGetSymbolAddress(&pq,   g_q);
    cudaGetSymbolAddress(&pk,   g_k);
    cudaGetSymbolAddress(&pv,   g_v);
    cudaGetSymbolAddress(&pctx, g_ctx);
    cudaGetSymbolAddress(&pwT,  g_wT);
    cudaGetSymbolAddress(&pxc,  g_xc);

    cudaFuncSetAttribute(attn_kernel,
                         cudaFuncAttributeMaxDynamicSharedMemorySize, ATTN_SMEM);
    cudaFuncSetAttribute(gemm_kernel,
                         cudaFuncAttributeMaxDynamicSharedMemorySize, GEMM_SMEM);

    transpose_cvt_kernel<<<dim3(32, 32, 4), dim3(32, 8)>>>(wq, wk, wv, wo);
    cvt_x_kernel<<<(MTOT * DMODEL) / (256 * 4), 256>>>(x);

    dim3 gblk(256);

    // fused QKV projections (z selects weight/output; V written transposed;
    // Q scale carries 0.125 * log2(e) for the exp2 softmax)
    gemm_kernel<<<dim3(DMODEL / 128, MTOT / 128, 3), gblk, GEMM_SMEM>>>(
        (const float*)pxc, (const float*)pwT,
        (float*)pq, (float*)pk, (float*)pv, nullptr, nullptr, 0);

    // causal flash attention
    attn_kernel<<<dim3(SLEN / 128, HEADS, BATCH), 256, ATTN_SMEM>>>();

    // output projection + bias
    gemm_kernel<<<dim3(DMODEL / 128, MTOT / 128, 1), gblk, GEMM_SMEM>>>(
        (const float*)pctx, (const float*)pwT,
        nullptr, nullptr, nullptr, out, bo, 1);
}

// round 16
// speedup vs baseline: 2.9477x; 1.0275x over previous
#include <cuda_runtime.h>
#include <math.h>
#include <stdint.h>

#define BATCH  2
#define SLEN   2048
#define DMODEL 1024
#define HEADS  16
#define DHEAD  64
#define MTOT   (BATCH * SLEN)   // 4096

// ---------------- scratch (device globals; no allocation allowed) ----------
__device__ float g_q[MTOT * DMODEL];
__device__ float g_k[MTOT * DMODEL];
__device__ float g_v[MTOT * DMODEL];          // V TRANSPOSED: [b][h][d][s]
__device__ float g_ctx[MTOT * DMODEL];
__device__ float g_xc[MTOT * DMODEL];         // x pre-rounded to tf32
__device__ float g_wT[4 * DMODEL * DMODEL];   // wq^T, wk^T, wv^T, wo^T (tf32)

// ---------------- helpers ---------------------------------------------------
__device__ __forceinline__ uint32_t to_tf32(float x) {
    uint32_t r;
    asm("cvt.rna.tf32.f32 %0, %1;" : "=r"(r) : "f"(x));
    return r;
}
__device__ __forceinline__ void mma_tf32(float c[4], const uint32_t a[4],
                                         const uint32_t b[2]) {
    asm volatile(
        "mma.sync.aligned.m16n8k8.row.col.f32.tf32.tf32.f32 "
        "{%0,%1,%2,%3}, {%4,%5,%6,%7}, {%8,%9}, {%0,%1,%2,%3};"
        : "+f"(c[0]), "+f"(c[1]), "+f"(c[2]), "+f"(c[3])
        : "r"(a[0]), "r"(a[1]), "r"(a[2]), "r"(a[3]), "r"(b[0]), "r"(b[1]));
}
__device__ __forceinline__ void ldsm_x4(uint32_t r[4], const void* p) {
    uint32_t a = (uint32_t)__cvta_generic_to_shared(p);
    asm volatile(
        "ldmatrix.sync.aligned.m8n8.x4.shared.b16 {%0,%1,%2,%3}, [%4];"
        : "=r"(r[0]), "=r"(r[1]), "=r"(r[2]), "=r"(r[3]) : "r"(a));
}
__device__ __forceinline__ void cp_async16(void* dst, const void* src) {
    uint32_t d = (uint32_t)__cvta_generic_to_shared(dst);
    asm volatile("cp.async.cg.shared.global [%0], [%1], 16;" :: "r"(d), "l"(src));
}
__device__ __forceinline__ void cp_commit() { asm volatile("cp.async.commit_group;"); }
__device__ __forceinline__ void cp_wait1()  { asm volatile("cp.async.wait_group 1;"); }
__device__ __forceinline__ void cp_wait0()  { asm volatile("cp.async.wait_group 0;"); }

// ===========================================================================
// prep kernels
// ===========================================================================
__global__ __launch_bounds__(256) void cvt_x_kernel(const float* __restrict__ x)
{
    const size_t i = ((size_t)blockIdx.x * 256 + threadIdx.x) * 4;
    float4 v = *(const float4*)(x + i);
    v.x = __uint_as_float(to_tf32(v.x));
    v.y = __uint_as_float(to_tf32(v.y));
    v.z = __uint_as_float(to_tf32(v.z));
    v.w = __uint_as_float(to_tf32(v.w));
    *(float4*)(g_xc + i) = v;
}

__global__ __launch_bounds__(256) void transpose_cvt_kernel(
    const float* __restrict__ w0, const float* __restrict__ w1,
    const float* __restrict__ w2, const float* __restrict__ w3)
{
    __shared__ float tile[32][33];
    const int z = blockIdx.z;
    const float* src = (z == 0) ? w0 : (z == 1) ? w1 : (z == 2) ? w2 : w3;
    float* dst = g_wT + (size_t)z * DMODEL * DMODEL;

    const int tx = threadIdx.x, ty = threadIdx.y;
    const int k0 = blockIdx.y * 32, n0 = blockIdx.x * 32;

#pragma unroll
    for (int i = 0; i < 4; i++)
        tile[ty + 8 * i][tx] = src[(size_t)(k0 + ty + 8 * i) * DMODEL + n0 + tx];
    __syncthreads();
#pragma unroll
    for (int i = 0; i < 4; i++)
        dst[(size_t)(n0 + ty + 8 * i) * DMODEL + k0 + tx] =
            __uint_as_float(to_tf32(tile[tx][ty + 8 * i]));
}

// ===========================================================================
// tf32 GEMM, 3-stage cp.async ring, ONE barrier per k-tile.
// phase 0: QKV fused; z==2 (V) writes TRANSPOSED per-head [b][h][d][s].
// phase 1: output projection (+bias), fp32.
// ===========================================================================
#define GP 36
#define GT_SIZE (128 * GP)
#define GEMM_SMEM (6 * GT_SIZE * (int)sizeof(float))   // 110592 B

__global__ __launch_bounds__(256, 2) void gemm_kernel(
    const float* __restrict__ A, const float* __restrict__ wTbase,
    float* __restrict__ outQ, float* __restrict__ outK,
    float* __restrict__ outV, float* __restrict__ outO,
    const float* __restrict__ bias, int phase)
{
    extern __shared__ float sm[];
    float* Ab[3] = { sm,           sm + 2*GT_SIZE, sm + 4*GT_SIZE };
    float* Bb[3] = { sm + GT_SIZE, sm + 3*GT_SIZE, sm + 5*GT_SIZE };

    const int z = blockIdx.z;
    const size_t WSZ = (size_t)DMODEL * DMODEL;
    const float* BT;
    float scale = 1.f;
    int roundOut;
    float* C;
    if (phase == 0) {
        BT = wTbase + (size_t)z * WSZ;
        roundOut = 1;
        // Q scale folds 1/sqrt(64) AND log2(e) for the exp2-based softmax
        if (z == 0)      { C = outQ; scale = 0.125f * 1.4426950408889634f; }
        else if (z == 1) { C = outK; }
        else             { C = outV; }
    } else {
        BT = wTbase + 3 * WSZ;
        C = outO; roundOut = 0;
    }

    const int t    = threadIdx.x;
    const int lane = t & 31;
    const int warp = t >> 5;
    const int m0   = blockIdx.y * 128;
    const int n0   = blockIdx.x * 128;
    const int wm   = (warp & 3) * 32;
    const int wn   = (warp >> 2) * 64;
    const int N = DMODEL, K = DMODEL;

    const int sr = t >> 3;
    const int sc = (t & 7) << 2;

    const float* Ag = A  + (size_t)m0 * K + sc;
    const float* Bg = BT + (size_t)n0 * K + sc;

    float acc[2][8][4];
#pragma unroll
    for (int mi = 0; mi < 2; mi++)
#pragma unroll
        for (int ni = 0; ni < 8; ni++)
#pragma unroll
            for (int r = 0; r < 4; r++) acc[mi][ni][r] = 0.f;

    const int nt = K / 32;

    auto stage = [&](int kt, int buf) {
        const int koff = kt * 32;
#pragma unroll
        for (int i = 0; i < 4; i++) {
            const int r = sr + i * 32;
            cp_async16(&Ab[buf][r * GP + sc], Ag + (size_t)r * K + koff);
            cp_async16(&Bb[buf][r * GP + sc], Bg + (size_t)r * K + koff);
        }
    };

    stage(0, 0); cp_commit();
    stage(1, 1); cp_commit();

    for (int kt = 0; kt < nt; kt++) {
        if (kt < nt - 1) cp_wait1(); else cp_wait0();
        __syncthreads();

        const int cur = kt - (kt / 3) * 3;   // kt % 3
        const float* As = Ab[cur];
        const float* Bs = Bb[cur];
        const float* abase = As + (lane & 15) * GP + ((lane >> 4) << 2);
        const float* bbase = Bs + (((lane >> 4) << 3) + (lane & 7)) * GP
                             + (((lane >> 3) & 1) << 2);
#pragma unroll
        for (int ks = 0; ks < 4; ks++) {
            const int k0 = ks * 8;
            uint32_t afr[2][4];
#pragma unroll
            for (int mi = 0; mi < 2; mi++)
                ldsm_x4(afr[mi], abase + (wm + mi * 16) * GP + k0);
#pragma unroll
            for (int np = 0; np < 4; np++) {
                uint32_t bfr[4];
                ldsm_x4(bfr, bbase + (wn + np * 16) * GP + k0);
#pragma unroll
                for (int mi = 0; mi < 2; mi++) {
                    mma_tf32(acc[mi][2 * np],     afr[mi], bfr);
                    mma_tf32(acc[mi][2 * np + 1], afr[mi], bfr + 2);
                }
            }
        }

        if (kt + 2 < nt) {
            const int nb = (kt + 2) - ((kt + 2) / 3) * 3;
            stage(kt + 2, nb);
            cp_commit();
        }
    }

    const bool vtrans = (phase == 0 && z == 2);
#pragma unroll
    for (int mi = 0; mi < 2; mi++) {
        const int row0 = m0 + wm + mi * 16 + (lane >> 2);
#pragma unroll
        for (int ni = 0; ni < 8; ni++) {
            const int col = n0 + wn + ni * 8 + ((lane & 3) << 1);
            float b0 = 0.f, b1 = 0.f;
            if (phase == 1 && bias) { b0 = bias[col]; b1 = bias[col + 1]; }
            float v00 = acc[mi][ni][0] * scale + b0;
            float v01 = acc[mi][ni][1] * scale + b1;
            float v10 = acc[mi][ni][2] * scale + b0;
            float v11 = acc[mi][ni][3] * scale + b1;
            if (roundOut) {
                v00 = __uint_as_float(to_tf32(v00));
                v01 = __uint_as_float(to_tf32(v01));
                v10 = __uint_as_float(to_tf32(v10));
                v11 = __uint_as_float(to_tf32(v11));
            }
            if (vtrans) {
                const int bb = row0 >> 11;          // / SLEN
                const int s  = row0 & (SLEN - 1);
                const int h  = col >> 6;
                const int d  = col & 63;
                float* vt = C + (((size_t)bb * HEADS + h) * DHEAD + d) * SLEN + s;
                vt[0]        = v00;
                vt[SLEN]     = v01;
                vt[8]        = v10;
                vt[SLEN + 8] = v11;
            } else {
                float2 a = {v00, v01}, b = {v10, v11};
                *(float2*)(C + (size_t)row0 * N + col) = a;
                *(float2*)(C + (size_t)(row0 + 8) * N + col) = b;
            }
        }
    }
}

// ===========================================================================
// Causal flash attention, tf32 mma. BQ=128, BK=64, 256 thr (8 warps).
// Round-11 interleaved inner loops (measured best) + exp2 softmax.
// V pre-transposed per head ([d][s]) -> PV symmetric with QK via ldmatrix.
// ===========================================================================
#define AP 68
#define ATTN_SMEM ((128 + 4 * 64) * AP * (int)sizeof(float))   // 104448 B

__global__ __launch_bounds__(256, 2) void attn_kernel()
{
    extern __shared__ float smf[];
    float* QPs = smf;                          // 128 x AP
    float* KsB[2]  = { smf + 128 * AP, smf + 256 * AP };
    float* VTsB[2] = { smf + 192 * AP, smf + 320 * AP };

    const int qt   = gridDim.x - 1 - blockIdx.x;   // heavy tiles first
    const int h    = blockIdx.y;
    const int b    = blockIdx.z;
    const int t    = threadIdx.x;
    const int lane = t & 31;
    const int w    = t >> 5;
    const int wbase = w * 16;

    const float* Qg  = g_q + ((size_t)b * SLEN + qt * 128) * DMODEL + h * DHEAD;
    const float* Kg  = g_k + (size_t)b * SLEN * DMODEL + h * DHEAD;
    const float* VTg = g_v + ((size_t)b * HEADS + h) * DHEAD * SLEN;  // [d][s]

    const int strow = t >> 4;            // 0..15
    const int stcol = (t & 15) << 2;     // 0..60
    const int vrow  = t >> 2;            // 0..63 (d)
    const int vcol4 = t & 3;

    auto stageKV = [&](int kt, int buf) {
#pragma unroll
        for (int i = 0; i < 4; i++) {
            const int r = strow + 16 * i;
            cp_async16(KsB[buf] + r * AP + stcol,
                       Kg + (size_t)(kt * 64 + r) * DMODEL + stcol);
        }
#pragma unroll
        for (int i = 0; i < 4; i++) {
            const int c = (vcol4 + 4 * i) << 2;
            cp_async16(VTsB[buf] + vrow * AP + c,
                       VTg + (size_t)vrow * SLEN + kt * 64 + c);
        }
    };

    // ---- stage Q (plain loads; already tf32) ----
#pragma unroll
    for (int i = 0; i < 8; i++) {
        const int r = strow + 16 * i;
        *(float4*)(QPs + r * AP + stcol) =
            *(const float4*)(Qg + (size_t)r * DMODEL + stcol);
    }

    stageKV(0, 0);
    cp_commit();
    __syncthreads();

    // ---- Q fragments into registers (QPs then free for P) ----
    uint32_t qa[8][4];
    {
        const float* base = QPs + (wbase + (lane & 15)) * AP + ((lane >> 4) << 2);
#pragma unroll
        for (int ds = 0; ds < 8; ds++)
            ldsm_x4(qa[ds], base + ds * 8);
    }

    float m0 = -1e30f, m1 = -1e30f, l0 = 0.f, l1 = 0.f;
    float O[8][4];
#pragma unroll
    for (int dn = 0; dn < 8; dn++)
#pragma unroll
        for (int r = 0; r < 4; r++) O[dn][r] = 0.f;

    const int r0 = lane >> 2;
    const int q2 = (lane & 3) << 1;
    const int ktmax = 2 * qt + 1;

    for (int kt = 0; kt <= ktmax; kt++) {
        if (kt < ktmax) { stageKV(kt + 1, (kt + 1) & 1); cp_commit(); cp_wait1(); }
        else            { cp_wait0(); }
        __syncthreads();

        const float* Ks  = KsB[kt & 1];
        const float* VTs = VTsB[kt & 1];
        const int off = kt * 64 - qt * 128;

        if (off <= wbase + 15) {
            // ---- S = Q @ K^T (round-11 interleaved pattern) ----
            float sacc[8][4];
#pragma unroll
            for (int n = 0; n < 8; n++)
#pragma unroll
                for (int r = 0; r < 4; r++) sacc[n][r] = 0.f;
            {
                const float* kbase = Ks + (((lane >> 4) << 3) + (lane & 7)) * AP
                                     + (((lane >> 3) & 1) << 2);
#pragma unroll
                for (int np = 0; np < 4; np++) {
#pragma unroll
                    for (int ds = 0; ds < 8; ds++) {
                        uint32_t kb[4];
                        ldsm_x4(kb, kbase + np * 16 * AP + ds * 8);
                        mma_tf32(sacc[2 * np],     qa[ds], kb);
                        mma_tf32(sacc[2 * np + 1], qa[ds], kb + 2);
                    }
                }
            }

            // ---- causal mask (boundary tiles) ----
            if (off + 63 > wbase) {
                const int rg0 = wbase + r0;
                const int rg1 = rg0 + 8;
#pragma unroll
                for (int n = 0; n < 8; n++) {
                    int c0 = off + n * 8 + q2;
                    if (c0     > rg0) sacc[n][0] = -1e30f;
                    if (c0 + 1 > rg0) sacc[n][1] = -1e30f;
                    if (c0     > rg1) sacc[n][2] = -1e30f;
                    if (c0 + 1 > rg1) sacc[n][3] = -1e30f;
                }
            }

            // ---- online softmax (base-2 domain) ----
            float mx0 = -1e30f, mx1 = -1e30f;
#pragma unroll
            for (int n = 0; n < 8; n++) {
                mx0 = fmaxf(mx0, fmaxf(sacc[n][0], sacc[n][1]));
                mx1 = fmaxf(mx1, fmaxf(sacc[n][2], sacc[n][3]));
            }
            mx0 = fmaxf(mx0, __shfl_xor_sync(0xffffffffu, mx0, 1));
            mx0 = fmaxf(mx0, __shfl_xor_sync(0xffffffffu, mx0, 2));
            mx1 = fmaxf(mx1, __shfl_xor_sync(0xffffffffu, mx1, 1));
            mx1 = fmaxf(mx1, __shfl_xor_sync(0xffffffffu, mx1, 2));

            const float nm0 = fmaxf(m0, mx0);
            const float nm1 = fmaxf(m1, mx1);
            const float a0  = exp2f(m0 - nm0);
            const float a1  = exp2f(m1 - nm1);
            float s0 = 0.f, s1 = 0.f;

            float* Prow0 = QPs + (wbase + r0) * AP + q2;
            float* Prow1 = Prow0 + 8 * AP;
#pragma unroll
            for (int n = 0; n < 8; n++) {
                float p00 = exp2f(sacc[n][0] - nm0);
                float p01 = exp2f(sacc[n][1] - nm0);
                float p10 = exp2f(sacc[n][2] - nm1);
                float p11 = exp2f(sacc[n][3] - nm1);
                s0 += p00 + p01;
                s1 += p10 + p11;
                float2 lo, hi;
                lo.x = __uint_as_float(to_tf32(p00));
                lo.y = __uint_as_float(to_tf32(p01));
                hi.x = __uint_as_float(to_tf32(p10));
                hi.y = __uint_as_float(to_tf32(p11));
                *(float2*)(Prow0 + n * 8) = lo;
                *(float2*)(Prow1 + n * 8) = hi;
            }
            s0 += __shfl_xor_sync(0xffffffffu, s0, 1);
            s0 += __shfl_xor_sync(0xffffffffu, s0, 2);
            s1 += __shfl_xor_sync(0xffffffffu, s1, 1);
            s1 += __shfl_xor_sync(0xffffffffu, s1, 2);

            l0 = l0 * a0 + s0;
            l1 = l1 * a1 + s1;
            m0 = nm0;
            m1 = nm1;
#pragma unroll
            for (int dn = 0; dn < 8; dn++) {
                O[dn][0] *= a0; O[dn][1] *= a0;
                O[dn][2] *= a1; O[dn][3] *= a1;
            }
            __syncwarp();

            // ---- O += P @ V (round-11 interleaved pattern, VT ldsm) ----
            {
                const float* pbase = QPs + (wbase + (lane & 15)) * AP
                                     + ((lane >> 4) << 2);
                const float* vtbase = VTs + (((lane >> 4) << 3) + (lane & 7)) * AP
                                      + (((lane >> 3) & 1) << 2);
#pragma unroll
                for (int ks = 0; ks < 8; ks++) {
                    uint32_t pa[4];
                    ldsm_x4(pa, pbase + ks * 8);
#pragma unroll
                    for (int np = 0; np < 4; np++) {
                        uint32_t vb[4];
                        ldsm_x4(vb, vtbase + np * 16 * AP + ks * 8);
                        mma_tf32(O[2 * np],     pa, vb);
                        mma_tf32(O[2 * np + 1], pa, vb + 2);
                    }
                }
            }
        }
        __syncthreads();   // buffer reads done before overwrite next iter
    }

    // ---- finalize & write context (tf32-rounded for the wo GEMM) ----
    const float inv0 = 1.f / l0;
    const float inv1 = 1.f / l1;
    const int rg0 = qt * 128 + wbase + r0;
    float* C0 = g_ctx + ((size_t)b * SLEN + rg0) * DMODEL + h * DHEAD + q2;
    float* C1 = C0 + 8 * DMODEL;
#pragma unroll
    for (int dn = 0; dn < 8; dn++) {
        float2 v0, v1;
        v0.x = __uint_as_float(to_tf32(O[dn][0] * inv0));
        v0.y = __uint_as_float(to_tf32(O[dn][1] * inv0));
        v1.x = __uint_as_float(to_tf32(O[dn][2] * inv1));
        v1.y = __uint_as_float(to_tf32(O[dn][3] * inv1));
        *(float2*)(C0 + dn * 8) = v0;
        *(float2*)(C1 + dn * 8) = v1;
    }
}

// ---------------------------------------------------------------------------
extern "C" void kernel_launch(void* const* d_in, const int* in_sizes, int n_in,
                              void* d_out, int out_size)
{
    const float* x  = (const float*)d_in[0];
    const float* wq = (const float*)d_in[1];
    const float* wk = (const float*)d_in[2];
    const float* wv = (const float*)d_in[3];
    const float* wo = (const float*)d_in[4];
    const float* bo = (const float*)d_in[5];
    float* out = (float*)d_out;

    void *pq, *pk, *pv, *pctx, *pwT, *pxc;
    cudaGetSymbolAddress(&pq,   g_q);
    cudaGetSymbolAddress(&pk,   g_k);
    cudaGetSymbolAddress(&pv,   g_v);
    cudaGetSymbolAddress(&pctx, g_ctx);
    cudaGetSymbolAddress(&pwT,  g_wT);
    cudaGetSymbolAddress(&pxc,  g_xc);

    cudaFuncSetAttribute(attn_kernel,
                         cudaFuncAttributeMaxDynamicSharedMemorySize, ATTN_SMEM);
    cudaFuncSetAttribute(gemm_kernel,
                         cudaFuncAttributeMaxDynamicSharedMemorySize, GEMM_SMEM);

    transpose_cvt_kernel<<<dim3(32, 32, 4), dim3(32, 8)>>>(wq, wk, wv, wo);
    cvt_x_kernel<<<(MTOT * DMODEL) / (256 * 4), 256>>>(x);

    dim3 gblk(256);

    // fused QKV projections (z selects weight/output; V written transposed;
    // Q scale carries 0.125 * log2(e) for the exp2 softmax)
    gemm_kernel<<<dim3(DMODEL / 128, MTOT / 128, 3), gblk, GEMM_SMEM>>>(
        (const float*)pxc, (const float*)pwT,
        (float*)pq, (float*)pk, (float*)pv, nullptr, nullptr, 0);

    // causal flash attention
    attn_kernel<<<dim3(SLEN / 128, HEADS, BATCH), 256, ATTN_SMEM>>>();

    // output projection + bias
    gemm_kernel<<<dim3(DMODEL / 128, MTOT / 128, 1), gblk, GEMM_SMEM>>>(
        (const float*)pctx, (const float*)pwT,
        nullptr, nullptr, nullptr, out, bo, 1);
}